// round 10
// baseline (speedup 1.0000x reference)
#include <cuda_runtime.h>
#include <cstdint>

#define NN   50000
#define EE   600000
#define FIN  128
#define HID  128
#define OUTC 64
#define EPSV 1e-9f
#define NHALF 25000

#define SCAN_B 256
#define SCAN_NB ((NN + SCAN_B - 1) / SCAN_B)   // 196

// ---------------- scratch (static device globals; no runtime allocation) ----
__device__ int   g_off [NN + 1];
__device__ int   g_cur [NN];
__device__ int   g_part[SCAN_NB];
__device__ int   g_ppre[SCAN_NB];
__device__ int   g_srcs[EE];
__device__ __align__(16) float g_y[(size_t)NN * HID];
__device__ __align__(16) float g_h[(size_t)NN * HID];
__device__ __align__(16) float g_z[(size_t)NN * OUTC];

// ---------------- threefry2x32, key = (0, 42) -------------------------------
__device__ __forceinline__ uint32_t tf_rotl(uint32_t x, int d) {
    return __funnelshift_l(x, x, d);
}

// JAX partitionable threefry random bits, bit_width=32:
//   counts = iota(uint64); x = (hi32=0, lo32=i); bits = o0 ^ o1
__device__ __forceinline__ uint32_t tf_bits32(uint32_t i) {
    const uint32_t k0 = 0u, k1 = 42u;
    const uint32_t k2 = 0u ^ 42u ^ 0x1BD11BDAu;
    uint32_t v0 = 0u + k0;
    uint32_t v1 = i  + k1;
#define TF_R(r) { v0 += v1; v1 = tf_rotl(v1, r); v1 ^= v0; }
    TF_R(13) TF_R(15) TF_R(26) TF_R(6)  v0 += k1; v1 += k2 + 1u;
    TF_R(17) TF_R(29) TF_R(16) TF_R(24) v0 += k2; v1 += k0 + 2u;
    TF_R(13) TF_R(15) TF_R(26) TF_R(6)  v0 += k0; v1 += k1 + 3u;
    TF_R(17) TF_R(29) TF_R(16) TF_R(24) v0 += k1; v1 += k2 + 4u;
    TF_R(13) TF_R(15) TF_R(26) TF_R(6)  v0 += k2; v1 += k0 + 5u;
#undef TF_R
    return v0 ^ v1;
}

__device__ __forceinline__ float drop_scale(uint32_t idx) {
    return (tf_bits32(idx) >> 31) ? 0.0f : 2.0f;
}

// ---------------- CSR build (edge_index is int32: src=[0,E), dst=[E,2E)) ---
__global__ void zero_deg_kernel() {
    int i = blockIdx.x * blockDim.x + threadIdx.x;
    if (i < NN) g_cur[i] = 0;
}

__global__ void hist_kernel(const int* __restrict__ ei) {
    int e = blockIdx.x * blockDim.x + threadIdx.x;
    if (e < EE) atomicAdd(&g_cur[ei[EE + e]], 1);
}

// ---- decoupled scan, stage 1: per-block sums of g_cur ----------------------
__global__ void scan_partial_kernel() {
    __shared__ int wsum[SCAN_B / 32];
    int i = blockIdx.x * SCAN_B + threadIdx.x;
    int v = (i < NN) ? g_cur[i] : 0;
    int s = v;
    #pragma unroll
    for (int o = 16; o > 0; o >>= 1) s += __shfl_down_sync(0xffffffffu, s, o);
    int lane = threadIdx.x & 31, w = threadIdx.x >> 5;
    if (lane == 0) wsum[w] = s;
    __syncthreads();
    if (w == 0) {
        int t = (lane < SCAN_B / 32) ? wsum[lane] : 0;
        #pragma unroll
        for (int o = 4; o > 0; o >>= 1) t += __shfl_down_sync(0xffffffffu, t, o);
        if (lane == 0) g_part[blockIdx.x] = t;
    }
}

// ---- stage 2: single block scans the 196 partials (exclusive) --------------
__global__ void scan_tops_kernel() {
    __shared__ int wpre[8];
    int t = threadIdx.x;                  // 256 threads
    int v = (t < SCAN_NB) ? g_part[t] : 0;
    int lane = t & 31, w = t >> 5;
    int inc = v;
    #pragma unroll
    for (int o = 1; o < 32; o <<= 1) {
        int u = __shfl_up_sync(0xffffffffu, inc, o);
        if (lane >= o) inc += u;
    }
    if (lane == 31) wpre[w] = inc;
    __syncthreads();
    if (w == 0) {
        int s = (lane < 8) ? wpre[lane] : 0;
        int si = s;
        #pragma unroll
        for (int o = 1; o < 8; o <<= 1) {
            int u = __shfl_up_sync(0xffffffffu, si, o);
            if (lane >= o) si += u;
        }
        if (lane < 8) wpre[lane] = si - s;   // exclusive warp prefix
        if (lane == 7) g_off[NN] = si;       // grand total
    }
    __syncthreads();
    if (t < SCAN_NB) g_ppre[t] = wpre[w] + inc - v;   // exclusive prefix
}

// ---- stage 3: per-block exclusive scan + base -> offsets/cursors -----------
__global__ void scan_offsets_kernel() {
    __shared__ int wpre[SCAN_B / 32];
    int i = blockIdx.x * SCAN_B + threadIdx.x;
    int v = (i < NN) ? g_cur[i] : 0;
    int lane = threadIdx.x & 31, w = threadIdx.x >> 5;
    int inc = v;
    #pragma unroll
    for (int o = 1; o < 32; o <<= 1) {
        int u = __shfl_up_sync(0xffffffffu, inc, o);
        if (lane >= o) inc += u;
    }
    if (lane == 31) wpre[w] = inc;
    __syncthreads();
    if (w == 0) {
        int s = (lane < SCAN_B / 32) ? wpre[lane] : 0;
        int si = s;
        #pragma unroll
        for (int o = 1; o < 8; o <<= 1) {
            int u = __shfl_up_sync(0xffffffffu, si, o);
            if (lane >= o) si += u;
        }
        if (lane < SCAN_B / 32) wpre[lane] = si - s;
    }
    __syncthreads();
    if (i < NN) {
        int o = g_ppre[blockIdx.x] + wpre[w] + (inc - v);
        g_off[i] = o;
        g_cur[i] = o;
    }
}

__global__ void bucket_kernel(const int* __restrict__ ei) {
    int e = blockIdx.x * blockDim.x + threadIdx.x;
    if (e < EE) {
        int d = ei[EE + e];
        int p = atomicAdd(&g_cur[d], 1);
        g_srcs[p] = ei[e];
    }
}

// ---------------- GEMM: C[rows rOff..rEnd, NC] = A @ W[128,NC] --------------
// block 256 thr, tile 64 rows x NC cols, thread = 8 rows x (NC/32) cols
template <int NC, bool LAYER2>
__global__ void __launch_bounds__(256)
gemm_kernel(const float* __restrict__ A_arg, const float* __restrict__ W,
            int rOff, int rEnd) {
    constexpr int CPT = NC / 32;               // 4 or 2 cols per thread
    __shared__ __align__(16) float As[64][20]; // row stride 80B (16B multiple)
    __shared__ __align__(16) float Ws[16 * NC];

    const float* __restrict__ A = LAYER2 ? (const float*)g_h : A_arg;
    float* __restrict__ C       = LAYER2 ? g_z : g_y;

    int t  = threadIdx.x;
    int rg = t >> 5;          // row group 0..7
    int cl = t & 31;          // lane -> column group
    int rowBase = rOff + blockIdx.x * 64;

    float acc[8][CPT];
    #pragma unroll
    for (int r = 0; r < 8; r++)
        #pragma unroll
        for (int c = 0; c < CPT; c++) acc[r][c] = 0.0f;

    for (int k0 = 0; k0 < 128; k0 += 16) {
        // load A 64x16 (one float4 per thread)
        {
            int r = t >> 2, q = t & 3;
            int grow = rowBase + r;
            float4 v = make_float4(0.f, 0.f, 0.f, 0.f);
            if (grow < rEnd) v = *(const float4*)&A[(size_t)grow * 128 + k0 + q * 4];
            *(float4*)&As[r][q * 4] = v;
        }
        // load W rows k0..k0+15 (contiguous chunk)
        {
            const float4* Wg = (const float4*)W;
            float4* Wsv = (float4*)Ws;
            #pragma unroll
            for (int i = t; i < 4 * NC; i += 256)
                Wsv[i] = Wg[(k0 * NC) / 4 + i];
        }
        __syncthreads();
        #pragma unroll
        for (int kq = 0; kq < 4; kq++) {       // 4 k at a time
            float w0[CPT], w1[CPT], w2[CPT], w3[CPT];
            if (CPT == 4) {
                float4 a_ = *(const float4*)&Ws[(kq * 4 + 0) * NC + cl * 4];
                float4 b_ = *(const float4*)&Ws[(kq * 4 + 1) * NC + cl * 4];
                float4 c_ = *(const float4*)&Ws[(kq * 4 + 2) * NC + cl * 4];
                float4 d_ = *(const float4*)&Ws[(kq * 4 + 3) * NC + cl * 4];
                w0[0]=a_.x; w0[1]=a_.y; w0[2]=a_.z; w0[3]=a_.w;
                w1[0]=b_.x; w1[1]=b_.y; w1[2]=b_.z; w1[3]=b_.w;
                w2[0]=c_.x; w2[1]=c_.y; w2[2]=c_.z; w2[3]=c_.w;
                w3[0]=d_.x; w3[1]=d_.y; w3[2]=d_.z; w3[3]=d_.w;
            } else {
                float2 a_ = *(const float2*)&Ws[(kq * 4 + 0) * NC + cl * 2];
                float2 b_ = *(const float2*)&Ws[(kq * 4 + 1) * NC + cl * 2];
                float2 c_ = *(const float2*)&Ws[(kq * 4 + 2) * NC + cl * 2];
                float2 d_ = *(const float2*)&Ws[(kq * 4 + 3) * NC + cl * 2];
                w0[0]=a_.x; w0[1]=a_.y;
                w1[0]=b_.x; w1[1]=b_.y;
                w2[0]=c_.x; w2[1]=c_.y;
                w3[0]=d_.x; w3[1]=d_.y;
            }
            #pragma unroll
            for (int r = 0; r < 8; r++) {
                float4 a = *(const float4*)&As[rg * 8 + r][kq * 4];  // broadcast
                #pragma unroll
                for (int c = 0; c < CPT; c++) {
                    acc[r][c] = fmaf(a.x, w0[c], acc[r][c]);
                    acc[r][c] = fmaf(a.y, w1[c], acc[r][c]);
                    acc[r][c] = fmaf(a.z, w2[c], acc[r][c]);
                    acc[r][c] = fmaf(a.w, w3[c], acc[r][c]);
                }
            }
        }
        __syncthreads();
    }
    // store
    #pragma unroll
    for (int r = 0; r < 8; r++) {
        int grow = rowBase + rg * 8 + r;
        if (grow < rEnd) {
            if (CPT == 4) {
                float4 v = make_float4(acc[r][0], acc[r][1], acc[r][2], acc[r][3]);
                *(float4*)&C[(size_t)grow * NC + cl * 4] = v;
            } else {
                float2 v = make_float2(acc[r][0], acc[r][1]);
                *(float2*)&C[(size_t)grow * NC + cl * 2] = v;
            }
        }
    }
}

// ---------------- layer-1 aggregate + bias + ReLU + dropout ----------------
// one warp per node over [nOff, nEnd), lane = 4 consecutive features
__global__ void __launch_bounds__(256)
agg_relu_drop_kernel(const float* __restrict__ b1, int nOff, int nEnd) {
    int gw = nOff + ((blockIdx.x * blockDim.x + threadIdx.x) >> 5);
    if (gw >= nEnd) return;
    int lane = threadIdx.x & 31;

    const float4* Y = (const float4*)g_y;
    float4 acc = Y[(size_t)gw * 32 + lane];
    float4 bb  = ((const float4*)b1)[lane];
    const float c1 = 1.0f + EPSV;
    acc.x = fmaf(acc.x, c1, bb.x);
    acc.y = fmaf(acc.y, c1, bb.y);
    acc.z = fmaf(acc.z, c1, bb.z);
    acc.w = fmaf(acc.w, c1, bb.w);

    int j = g_off[gw], end = g_off[gw + 1];
    for (; j + 4 <= end; j += 4) {
        int s0 = g_srcs[j], s1 = g_srcs[j + 1], s2 = g_srcs[j + 2], s3 = g_srcs[j + 3];
        float4 v0 = Y[(size_t)s0 * 32 + lane];
        float4 v1 = Y[(size_t)s1 * 32 + lane];
        float4 v2 = Y[(size_t)s2 * 32 + lane];
        float4 v3 = Y[(size_t)s3 * 32 + lane];
        acc.x += (v0.x + v1.x) + (v2.x + v3.x);
        acc.y += (v0.y + v1.y) + (v2.y + v3.y);
        acc.z += (v0.z + v1.z) + (v2.z + v3.z);
        acc.w += (v0.w + v1.w) + (v2.w + v3.w);
    }
    for (; j < end; j++) {
        float4 v = Y[(size_t)g_srcs[j] * 32 + lane];
        acc.x += v.x; acc.y += v.y; acc.z += v.z; acc.w += v.w;
    }

    acc.x = fmaxf(acc.x, 0.f);
    acc.y = fmaxf(acc.y, 0.f);
    acc.z = fmaxf(acc.z, 0.f);
    acc.w = fmaxf(acc.w, 0.f);

    uint32_t base = (uint32_t)gw * 128u + (uint32_t)lane * 4u;
    acc.x *= drop_scale(base + 0u);
    acc.y *= drop_scale(base + 1u);
    acc.z *= drop_scale(base + 2u);
    acc.w *= drop_scale(base + 3u);

    ((float4*)g_h)[(size_t)gw * 32 + lane] = acc;
}

// ---------------- layer-2 aggregate + bias -> output -----------------------
__global__ void __launch_bounds__(256)
agg_out_kernel(const float* __restrict__ b2, float* __restrict__ out) {
    int gw = (blockIdx.x * blockDim.x + threadIdx.x) >> 5;
    if (gw >= NN) return;
    int lane = threadIdx.x & 31;

    const float2* Z = (const float2*)g_z;
    float2 acc = Z[(size_t)gw * 32 + lane];
    float2 bb  = ((const float2*)b2)[lane];
    const float c1 = 1.0f + EPSV;
    acc.x = fmaf(acc.x, c1, bb.x);
    acc.y = fmaf(acc.y, c1, bb.y);

    int j = g_off[gw], end = g_off[gw + 1];
    for (; j + 4 <= end; j += 4) {
        int s0 = g_srcs[j], s1 = g_srcs[j + 1], s2 = g_srcs[j + 2], s3 = g_srcs[j + 3];
        float2 v0 = Z[(size_t)s0 * 32 + lane];
        float2 v1 = Z[(size_t)s1 * 32 + lane];
        float2 v2 = Z[(size_t)s2 * 32 + lane];
        float2 v3 = Z[(size_t)s3 * 32 + lane];
        acc.x += (v0.x + v1.x) + (v2.x + v3.x);
        acc.y += (v0.y + v1.y) + (v2.y + v3.y);
    }
    for (; j < end; j++) {
        float2 v = Z[(size_t)g_srcs[j] * 32 + lane];
        acc.x += v.x; acc.y += v.y;
    }

    ((float2*)out)[(size_t)gw * 32 + lane] = acc;
}

// ---------------- launch: fork CSR || GEMM1, then agg1/GEMM2 pipeline -------
extern "C" void kernel_launch(void* const* d_in, const int* in_sizes, int n_in,
                              void* d_out, int out_size) {
    const float* x  = (const float*)d_in[0];
    const int*   ei = (const int*)d_in[1];     // int32 (JAX x64 disabled)
    const float* W1 = (const float*)d_in[2];
    const float* b1 = (const float*)d_in[3];
    const float* W2 = (const float*)d_in[4];
    const float* b2 = (const float*)d_in[5];
    float*       out = (float*)d_out;

    // ONE side stream + lightweight events (capture-safe fork/join). Created
    // fresh each call and intentionally NOT destroyed (destroying during an
    // active capture invalidates it). One stream/call stays inside the
    // driver's pre-allocated pool (two per call tripped the teardown check).
    cudaStream_t s2;
    cudaStreamCreate(&s2);
    cudaEvent_t eFork, eCSR, eY, eH1;
    cudaEventCreateWithFlags(&eFork, cudaEventDisableTiming);
    cudaEventCreateWithFlags(&eCSR,  cudaEventDisableTiming);
    cudaEventCreateWithFlags(&eY,    cudaEventDisableTiming);
    cudaEventCreateWithFlags(&eH1,   cudaEventDisableTiming);

    // fork
    cudaEventRecord(eFork, 0);
    cudaStreamWaitEvent(s2, eFork, 0);

    // branch A (s2): CSR build (shared by both layers)
    zero_deg_kernel<<<(NN + 255) / 256, 256, 0, s2>>>();
    hist_kernel<<<(EE + 255) / 256, 256, 0, s2>>>(ei);
    scan_partial_kernel<<<SCAN_NB, SCAN_B, 0, s2>>>();
    scan_tops_kernel<<<1, 256, 0, s2>>>();
    scan_offsets_kernel<<<SCAN_NB, SCAN_B, 0, s2>>>();
    bucket_kernel<<<(EE + 255) / 256, 256, 0, s2>>>(ei);
    cudaEventRecord(eCSR, s2);

    // branch B (default): y = x@W1
    gemm_kernel<128, false><<<(NN + 63) / 64, 256>>>(x, W1, 0, NN);

    // join CSR into default; mark "y + CSR ready"
    cudaStreamWaitEvent(0, eCSR, 0);
    cudaEventRecord(eY, 0);

    // pipeline: agg1 half0 (stream 0), then GEMM2 half0 (stream 0, fma)
    //           concurrent with agg1 half1 (s2, L2-gather)
    agg_relu_drop_kernel<<<(NHALF * 32 + 255) / 256, 256>>>(b1, 0, NHALF);

    cudaStreamWaitEvent(s2, eY, 0);
    agg_relu_drop_kernel<<<(NHALF * 32 + 255) / 256, 256, 0, s2>>>(b1, NHALF, NN);
    cudaEventRecord(eH1, s2);

    gemm_kernel<64, true><<<(NHALF + 63) / 64, 256>>>(nullptr, W2, 0, NHALF);

    cudaStreamWaitEvent(0, eH1, 0);
    gemm_kernel<64, true><<<(NN - NHALF + 63) / 64, 256>>>(nullptr, W2, NHALF, NN);

    // final: out = (1+eps)z + seg_sum(z[src]) + b2
    agg_out_kernel<<<(NN * 32 + 255) / 256, 256>>>(b2, out);
}

// round 11
// speedup vs baseline: 1.5180x; 1.5180x over previous
#include <cuda_runtime.h>
#include <cstdint>

#define NN   50000
#define EE   600000
#define FIN  128
#define HID  128
#define OUTC 64
#define EPSV 1e-9f

#define SCAN_B 256
#define SCAN_NB ((NN + SCAN_B - 1) / SCAN_B)   // 196

// ---------------- scratch (static device globals; no runtime allocation) ----
__device__ int   g_off [NN + 1];
__device__ int   g_cur [NN];
__device__ int   g_part[SCAN_NB];
__device__ int   g_ppre[SCAN_NB];
__device__ int   g_srcs[EE];
__device__ __align__(16) float g_y[(size_t)NN * HID];
__device__ __align__(16) float g_z[(size_t)NN * OUTC];

// ---------------- threefry2x32, key = (0, 42) -------------------------------
__device__ __forceinline__ uint32_t tf_rotl(uint32_t x, int d) {
    return __funnelshift_l(x, x, d);
}

// JAX partitionable threefry random bits, bit_width=32:
//   counts = iota(uint64); x = (hi32=0, lo32=i); bits = o0 ^ o1
__device__ __forceinline__ uint32_t tf_bits32(uint32_t i) {
    const uint32_t k0 = 0u, k1 = 42u;
    const uint32_t k2 = 0u ^ 42u ^ 0x1BD11BDAu;
    uint32_t v0 = 0u + k0;
    uint32_t v1 = i  + k1;
#define TF_R(r) { v0 += v1; v1 = tf_rotl(v1, r); v1 ^= v0; }
    TF_R(13) TF_R(15) TF_R(26) TF_R(6)  v0 += k1; v1 += k2 + 1u;
    TF_R(17) TF_R(29) TF_R(16) TF_R(24) v0 += k2; v1 += k0 + 2u;
    TF_R(13) TF_R(15) TF_R(26) TF_R(6)  v0 += k0; v1 += k1 + 3u;
    TF_R(17) TF_R(29) TF_R(16) TF_R(24) v0 += k1; v1 += k2 + 4u;
    TF_R(13) TF_R(15) TF_R(26) TF_R(6)  v0 += k2; v1 += k0 + 5u;
#undef TF_R
    return v0 ^ v1;
}

__device__ __forceinline__ float drop_scale(uint32_t idx) {
    return (tf_bits32(idx) >> 31) ? 0.0f : 2.0f;
}

// ---------------- CSR build (edge_index is int32: src=[0,E), dst=[E,2E)) ---
__global__ void zero_deg_kernel() {
    int i = blockIdx.x * blockDim.x + threadIdx.x;
    if (i < NN) g_cur[i] = 0;
}

__global__ void hist_kernel(const int* __restrict__ ei) {
    int e = blockIdx.x * blockDim.x + threadIdx.x;
    if (e < EE) atomicAdd(&g_cur[ei[EE + e]], 1);
}

// ---- decoupled scan, stage 1: per-block sums of g_cur ----------------------
__global__ void scan_partial_kernel() {
    __shared__ int wsum[SCAN_B / 32];
    int i = blockIdx.x * SCAN_B + threadIdx.x;
    int v = (i < NN) ? g_cur[i] : 0;
    int s = v;
    #pragma unroll
    for (int o = 16; o > 0; o >>= 1) s += __shfl_down_sync(0xffffffffu, s, o);
    int lane = threadIdx.x & 31, w = threadIdx.x >> 5;
    if (lane == 0) wsum[w] = s;
    __syncthreads();
    if (w == 0) {
        int t = (lane < SCAN_B / 32) ? wsum[lane] : 0;
        #pragma unroll
        for (int o = 4; o > 0; o >>= 1) t += __shfl_down_sync(0xffffffffu, t, o);
        if (lane == 0) g_part[blockIdx.x] = t;
    }
}

// ---- stage 2: single block scans the 196 partials (exclusive) --------------
__global__ void scan_tops_kernel() {
    __shared__ int wpre[8];
    int t = threadIdx.x;                  // 256 threads
    int v = (t < SCAN_NB) ? g_part[t] : 0;
    int lane = t & 31, w = t >> 5;
    int inc = v;
    #pragma unroll
    for (int o = 1; o < 32; o <<= 1) {
        int u = __shfl_up_sync(0xffffffffu, inc, o);
        if (lane >= o) inc += u;
    }
    if (lane == 31) wpre[w] = inc;
    __syncthreads();
    if (w == 0) {
        int s = (lane < 8) ? wpre[lane] : 0;
        int si = s;
        #pragma unroll
        for (int o = 1; o < 8; o <<= 1) {
            int u = __shfl_up_sync(0xffffffffu, si, o);
            if (lane >= o) si += u;
        }
        if (lane < 8) wpre[lane] = si - s;   // exclusive warp prefix
        if (lane == 7) g_off[NN] = si;       // grand total
    }
    __syncthreads();
    if (t < SCAN_NB) g_ppre[t] = wpre[w] + inc - v;   // exclusive prefix
}

// ---- stage 3: per-block exclusive scan + base -> offsets/cursors -----------
__global__ void scan_offsets_kernel() {
    __shared__ int wpre[SCAN_B / 32];
    int i = blockIdx.x * SCAN_B + threadIdx.x;
    int v = (i < NN) ? g_cur[i] : 0;
    int lane = threadIdx.x & 31, w = threadIdx.x >> 5;
    int inc = v;
    #pragma unroll
    for (int o = 1; o < 32; o <<= 1) {
        int u = __shfl_up_sync(0xffffffffu, inc, o);
        if (lane >= o) inc += u;
    }
    if (lane == 31) wpre[w] = inc;
    __syncthreads();
    if (w == 0) {
        int s = (lane < SCAN_B / 32) ? wpre[lane] : 0;
        int si = s;
        #pragma unroll
        for (int o = 1; o < 8; o <<= 1) {
            int u = __shfl_up_sync(0xffffffffu, si, o);
            if (lane >= o) si += u;
        }
        if (lane < SCAN_B / 32) wpre[lane] = si - s;
    }
    __syncthreads();
    if (i < NN) {
        int o = g_ppre[blockIdx.x] + wpre[w] + (inc - v);
        g_off[i] = o;
        g_cur[i] = o;
    }
}

__global__ void bucket_kernel(const int* __restrict__ ei) {
    int e = blockIdx.x * blockDim.x + threadIdx.x;
    if (e < EE) {
        int d = ei[EE + e];
        int p = atomicAdd(&g_cur[d], 1);
        g_srcs[p] = ei[e];
    }
}

// ---------------- GEMM1: g_y[M,128] = A[M,128] @ W1[128,128] ---------------
// block 256 thr, tile 64 rows x 128 cols, thread = 8 rows x 4 cols
__global__ void __launch_bounds__(256)
gemm1_kernel(const float* __restrict__ A, const float* __restrict__ W, int M) {
    __shared__ __align__(16) float As[64][20]; // row stride 80B (16B multiple)
    __shared__ __align__(16) float Ws[16 * 128];

    float* __restrict__ C = g_y;

    int t  = threadIdx.x;
    int rg = t >> 5;          // row group 0..7
    int cl = t & 31;          // lane -> column group
    int rowBase = blockIdx.x * 64;

    float acc[8][4];
    #pragma unroll
    for (int r = 0; r < 8; r++)
        #pragma unroll
        for (int c = 0; c < 4; c++) acc[r][c] = 0.0f;

    for (int k0 = 0; k0 < 128; k0 += 16) {
        // load A 64x16 (one float4 per thread)
        {
            int r = t >> 2, q = t & 3;
            int grow = rowBase + r;
            float4 v = make_float4(0.f, 0.f, 0.f, 0.f);
            if (grow < M) v = *(const float4*)&A[(size_t)grow * 128 + k0 + q * 4];
            *(float4*)&As[r][q * 4] = v;
        }
        // load W rows k0..k0+15
        {
            const float4* Wg = (const float4*)W;
            float4* Wsv = (float4*)Ws;
            #pragma unroll
            for (int i = t; i < 512; i += 256)
                Wsv[i] = Wg[(k0 * 128) / 4 + i];
        }
        __syncthreads();
        #pragma unroll
        for (int kq = 0; kq < 4; kq++) {       // 4 k at a time
            float4 a_ = *(const float4*)&Ws[(kq * 4 + 0) * 128 + cl * 4];
            float4 b_ = *(const float4*)&Ws[(kq * 4 + 1) * 128 + cl * 4];
            float4 c_ = *(const float4*)&Ws[(kq * 4 + 2) * 128 + cl * 4];
            float4 d_ = *(const float4*)&Ws[(kq * 4 + 3) * 128 + cl * 4];
            float w0[4] = {a_.x, a_.y, a_.z, a_.w};
            float w1[4] = {b_.x, b_.y, b_.z, b_.w};
            float w2[4] = {c_.x, c_.y, c_.z, c_.w};
            float w3[4] = {d_.x, d_.y, d_.z, d_.w};
            #pragma unroll
            for (int r = 0; r < 8; r++) {
                float4 a = *(const float4*)&As[rg * 8 + r][kq * 4];  // broadcast
                #pragma unroll
                for (int c = 0; c < 4; c++) {
                    acc[r][c] = fmaf(a.x, w0[c], acc[r][c]);
                    acc[r][c] = fmaf(a.y, w1[c], acc[r][c]);
                    acc[r][c] = fmaf(a.z, w2[c], acc[r][c]);
                    acc[r][c] = fmaf(a.w, w3[c], acc[r][c]);
                }
            }
        }
        __syncthreads();
    }
    #pragma unroll
    for (int r = 0; r < 8; r++) {
        int grow = rowBase + rg * 8 + r;
        if (grow < M) {
            float4 v = make_float4(acc[r][0], acc[r][1], acc[r][2], acc[r][3]);
            *(float4*)&C[(size_t)grow * 128 + cl * 4] = v;
        }
    }
}

// ---------------- FUSED: agg1 (gather+relu+dropout) -> GEMM2 ----------------
// block 256 thr, 64 nodes/block.
// phase 1: warp w builds h rows for nodes [base+w*8, base+w*8+8) into smem
// phase 2: z tile [64,64] = Hs @ W2 (same inner loop as before)
__global__ void __launch_bounds__(256)
fused_agg_gemm2_kernel(const float* __restrict__ b1, const float* __restrict__ W2) {
    __shared__ __align__(16) float Hs[64][132];   // 528B row stride (16B mult.)
    __shared__ __align__(16) float Ws[16 * 64];

    int t = threadIdx.x;
    int lane = t & 31;
    int w = t >> 5;            // warp 0..7
    int rowBase = blockIdx.x * 64;

    // ---- phase 1: aggregate + bias + ReLU + dropout into Hs ----
    {
        const float4* Y = (const float4*)g_y;
        float4 bb = ((const float4*)b1)[lane];
        const float c1 = 1.0f + EPSV;
        #pragma unroll 1
        for (int i = 0; i < 8; i++) {
            int node = rowBase + w * 8 + i;
            float4 acc = make_float4(0.f, 0.f, 0.f, 0.f);
            if (node < NN) {
                acc = Y[(size_t)node * 32 + lane];
                acc.x = fmaf(acc.x, c1, bb.x);
                acc.y = fmaf(acc.y, c1, bb.y);
                acc.z = fmaf(acc.z, c1, bb.z);
                acc.w = fmaf(acc.w, c1, bb.w);

                int j = g_off[node], end = g_off[node + 1];
                for (; j + 4 <= end; j += 4) {
                    int s0 = g_srcs[j], s1 = g_srcs[j + 1];
                    int s2 = g_srcs[j + 2], s3 = g_srcs[j + 3];
                    float4 v0 = Y[(size_t)s0 * 32 + lane];
                    float4 v1 = Y[(size_t)s1 * 32 + lane];
                    float4 v2 = Y[(size_t)s2 * 32 + lane];
                    float4 v3 = Y[(size_t)s3 * 32 + lane];
                    acc.x += (v0.x + v1.x) + (v2.x + v3.x);
                    acc.y += (v0.y + v1.y) + (v2.y + v3.y);
                    acc.z += (v0.z + v1.z) + (v2.z + v3.z);
                    acc.w += (v0.w + v1.w) + (v2.w + v3.w);
                }
                for (; j < end; j++) {
                    float4 v = Y[(size_t)g_srcs[j] * 32 + lane];
                    acc.x += v.x; acc.y += v.y; acc.z += v.z; acc.w += v.w;
                }

                acc.x = fmaxf(acc.x, 0.f);
                acc.y = fmaxf(acc.y, 0.f);
                acc.z = fmaxf(acc.z, 0.f);
                acc.w = fmaxf(acc.w, 0.f);

                uint32_t base = (uint32_t)node * 128u + (uint32_t)lane * 4u;
                acc.x *= drop_scale(base + 0u);
                acc.y *= drop_scale(base + 1u);
                acc.z *= drop_scale(base + 2u);
                acc.w *= drop_scale(base + 3u);
            }
            *(float4*)&Hs[w * 8 + i][lane * 4] = acc;
        }
    }
    __syncthreads();

    // ---- phase 2: z = Hs @ W2  (thread = 8 rows x 2 cols) ----
    int rg = w;
    int cl = lane;
    float acc[8][2];
    #pragma unroll
    for (int r = 0; r < 8; r++) { acc[r][0] = 0.f; acc[r][1] = 0.f; }

    for (int k0 = 0; k0 < 128; k0 += 16) {
        // load W2 rows k0..k0+15 (16x64 floats = 256 float4, 1/thread)
        {
            const float4* Wg = (const float4*)W2;
            ((float4*)Ws)[t] = Wg[(k0 * 64) / 4 + t];
        }
        __syncthreads();
        #pragma unroll
        for (int kq = 0; kq < 4; kq++) {
            float2 a_ = *(const float2*)&Ws[(kq * 4 + 0) * 64 + cl * 2];
            float2 b_ = *(const float2*)&Ws[(kq * 4 + 1) * 64 + cl * 2];
            float2 c_ = *(const float2*)&Ws[(kq * 4 + 2) * 64 + cl * 2];
            float2 d_ = *(const float2*)&Ws[(kq * 4 + 3) * 64 + cl * 2];
            float w0[2] = {a_.x, a_.y};
            float w1[2] = {b_.x, b_.y};
            float w2[2] = {c_.x, c_.y};
            float w3[2] = {d_.x, d_.y};
            #pragma unroll
            for (int r = 0; r < 8; r++) {
                float4 a = *(const float4*)&Hs[rg * 8 + r][k0 + kq * 4]; // bcast
                #pragma unroll
                for (int c = 0; c < 2; c++) {
                    acc[r][c] = fmaf(a.x, w0[c], acc[r][c]);
                    acc[r][c] = fmaf(a.y, w1[c], acc[r][c]);
                    acc[r][c] = fmaf(a.z, w2[c], acc[r][c]);
                    acc[r][c] = fmaf(a.w, w3[c], acc[r][c]);
                }
            }
        }
        __syncthreads();
    }
    #pragma unroll
    for (int r = 0; r < 8; r++) {
        int grow = rowBase + rg * 8 + r;
        if (grow < NN) {
            float2 v = make_float2(acc[r][0], acc[r][1]);
            *(float2*)&g_z[(size_t)grow * 64 + cl * 2] = v;
        }
    }
}

// ---------------- layer-2 aggregate + bias -> output -----------------------
__global__ void __launch_bounds__(256)
agg_out_kernel(const float* __restrict__ b2, float* __restrict__ out) {
    int gw = (blockIdx.x * blockDim.x + threadIdx.x) >> 5;
    if (gw >= NN) return;
    int lane = threadIdx.x & 31;

    const float2* Z = (const float2*)g_z;
    float2 acc = Z[(size_t)gw * 32 + lane];
    float2 bb  = ((const float2*)b2)[lane];
    const float c1 = 1.0f + EPSV;
    acc.x = fmaf(acc.x, c1, bb.x);
    acc.y = fmaf(acc.y, c1, bb.y);

    int j = g_off[gw], end = g_off[gw + 1];
    for (; j + 4 <= end; j += 4) {
        int s0 = g_srcs[j], s1 = g_srcs[j + 1], s2 = g_srcs[j + 2], s3 = g_srcs[j + 3];
        float2 v0 = Z[(size_t)s0 * 32 + lane];
        float2 v1 = Z[(size_t)s1 * 32 + lane];
        float2 v2 = Z[(size_t)s2 * 32 + lane];
        float2 v3 = Z[(size_t)s3 * 32 + lane];
        acc.x += (v0.x + v1.x) + (v2.x + v3.x);
        acc.y += (v0.y + v1.y) + (v2.y + v3.y);
    }
    for (; j < end; j++) {
        float2 v = Z[(size_t)g_srcs[j] * 32 + lane];
        acc.x += v.x; acc.y += v.y;
    }

    ((float2*)out)[(size_t)gw * 32 + lane] = acc;
}

// ---------------- launch: fork CSR || GEMM1; fused agg+GEMM2; agg_out -------
extern "C" void kernel_launch(void* const* d_in, const int* in_sizes, int n_in,
                              void* d_out, int out_size) {
    const float* x  = (const float*)d_in[0];
    const int*   ei = (const int*)d_in[1];     // int32 (JAX x64 disabled)
    const float* W1 = (const float*)d_in[2];
    const float* b1 = (const float*)d_in[3];
    const float* W2 = (const float*)d_in[4];
    const float* b2 = (const float*)d_in[5];
    float*       out = (float*)d_out;

    // ONE side stream + lightweight events (capture-safe fork/join). Created
    // fresh each call and intentionally NOT destroyed (destroying during an
    // active capture invalidates it; one stream/call stays inside the
    // driver's pre-allocated pool — two per call tripped the teardown check).
    cudaStream_t s2;
    cudaStreamCreate(&s2);
    cudaEvent_t eFork, eCSR;
    cudaEventCreateWithFlags(&eFork, cudaEventDisableTiming);
    cudaEventCreateWithFlags(&eCSR,  cudaEventDisableTiming);

    // fork
    cudaEventRecord(eFork, 0);
    cudaStreamWaitEvent(s2, eFork, 0);

    // branch A (s2): CSR build (shared by both layers)
    zero_deg_kernel<<<(NN + 255) / 256, 256, 0, s2>>>();
    hist_kernel<<<(EE + 255) / 256, 256, 0, s2>>>(ei);
    scan_partial_kernel<<<SCAN_NB, SCAN_B, 0, s2>>>();
    scan_tops_kernel<<<1, 256, 0, s2>>>();
    scan_offsets_kernel<<<SCAN_NB, SCAN_B, 0, s2>>>();
    bucket_kernel<<<(EE + 255) / 256, 256, 0, s2>>>(ei);
    cudaEventRecord(eCSR, s2);

    // branch B (default): y = x@W1
    gemm1_kernel<<<(NN + 63) / 64, 256>>>(x, W1, NN);

    // join: fused kernel needs CSR + y
    cudaStreamWaitEvent(0, eCSR, 0);

    // fused: h = dropout(relu((1+eps)y + seg_sum(y[src]) + b1)); z = h@W2
    fused_agg_gemm2_kernel<<<(NN + 63) / 64, 256>>>(b1, W2);

    // final: out = (1+eps)z + seg_sum(z[src]) + b2
    agg_out_kernel<<<(NN * 32 + 255) / 256, 256>>>(b2, out);
}

// round 13
// speedup vs baseline: 1.5635x; 1.0300x over previous
#include <cuda_runtime.h>
#include <cuda_bf16.h>
#include <cstdint>

#define NN   50000
#define EE   600000
#define FIN  128
#define HID  128
#define OUTC 64
#define EPSV 1e-9f

#define SCAN_B 256
#define SCAN_NB ((NN + SCAN_B - 1) / SCAN_B)   // 196

// ---------------- scratch (static device globals; no runtime allocation) ----
__device__ int   g_off [NN + 1];
__device__ int   g_cur [NN];
__device__ int   g_part[SCAN_NB];
__device__ int   g_ppre[SCAN_NB];
__device__ int   g_srcs[EE];
__device__ __align__(16) float g_y[(size_t)NN * HID];
__device__ __align__(16) float g_h[(size_t)NN * HID];
__device__ __align__(16) float g_z[(size_t)NN * OUTC];

// ---------------- threefry2x32, key = (0, 42) -------------------------------
__device__ __forceinline__ uint32_t tf_rotl(uint32_t x, int d) {
    return __funnelshift_l(x, x, d);
}

__device__ __forceinline__ uint32_t tf_bits32(uint32_t i) {
    const uint32_t k0 = 0u, k1 = 42u;
    const uint32_t k2 = 0u ^ 42u ^ 0x1BD11BDAu;
    uint32_t v0 = 0u + k0;
    uint32_t v1 = i  + k1;
#define TF_R(r) { v0 += v1; v1 = tf_rotl(v1, r); v1 ^= v0; }
    TF_R(13) TF_R(15) TF_R(26) TF_R(6)  v0 += k1; v1 += k2 + 1u;
    TF_R(17) TF_R(29) TF_R(16) TF_R(24) v0 += k2; v1 += k0 + 2u;
    TF_R(13) TF_R(15) TF_R(26) TF_R(6)  v0 += k0; v1 += k1 + 3u;
    TF_R(17) TF_R(29) TF_R(16) TF_R(24) v0 += k1; v1 += k2 + 4u;
    TF_R(13) TF_R(15) TF_R(26) TF_R(6)  v0 += k2; v1 += k0 + 5u;
#undef TF_R
    return v0 ^ v1;
}

__device__ __forceinline__ float drop_scale(uint32_t idx) {
    return (tf_bits32(idx) >> 31) ? 0.0f : 2.0f;
}

// ---------------- warp-MMA helpers (sm_80-era path; valid on compute_103) ---
__device__ __forceinline__ uint32_t smem_u32(const void* p) {
    uint32_t a;
    asm("{ .reg .u64 t; cvta.to.shared.u64 t, %1; cvt.u32.u64 %0, t; }"
        : "=r"(a) : "l"(p));
    return a;
}

#define LDSM_X4(r0, r1, r2, r3, addr) \
    asm volatile("ldmatrix.sync.aligned.m8n8.x4.shared.b16 {%0,%1,%2,%3}, [%4];" \
        : "=r"(r0), "=r"(r1), "=r"(r2), "=r"(r3) : "r"(addr))

#define MMA_BF16(d, a, b0, b1) \
    asm volatile("mma.sync.aligned.m16n8k16.row.col.f32.bf16.bf16.f32 " \
        "{%0,%1,%2,%3}, {%4,%5,%6,%7}, {%8,%9}, {%0,%1,%2,%3};" \
        : "+f"((d)[0]), "+f"((d)[1]), "+f"((d)[2]), "+f"((d)[3]) \
        : "r"((a)[0]), "r"((a)[1]), "r"((a)[2]), "r"((a)[3]), \
          "r"(b0), "r"(b1))

// ---------------- CSR build (edge_index is int32: src=[0,E), dst=[E,2E)) ---
__global__ void zero_deg_kernel() {
    int i = blockIdx.x * blockDim.x + threadIdx.x;
    if (i < NN) g_cur[i] = 0;
}

__global__ void hist_kernel(const int* __restrict__ ei) {
    int e = blockIdx.x * blockDim.x + threadIdx.x;
    if (e < EE) atomicAdd(&g_cur[ei[EE + e]], 1);
}

__global__ void scan_partial_kernel() {
    __shared__ int wsum[SCAN_B / 32];
    int i = blockIdx.x * SCAN_B + threadIdx.x;
    int v = (i < NN) ? g_cur[i] : 0;
    int s = v;
    #pragma unroll
    for (int o = 16; o > 0; o >>= 1) s += __shfl_down_sync(0xffffffffu, s, o);
    int lane = threadIdx.x & 31, w = threadIdx.x >> 5;
    if (lane == 0) wsum[w] = s;
    __syncthreads();
    if (w == 0) {
        int t = (lane < SCAN_B / 32) ? wsum[lane] : 0;
        #pragma unroll
        for (int o = 4; o > 0; o >>= 1) t += __shfl_down_sync(0xffffffffu, t, o);
        if (lane == 0) g_part[blockIdx.x] = t;
    }
}

__global__ void scan_tops_kernel() {
    __shared__ int wpre[8];
    int t = threadIdx.x;
    int v = (t < SCAN_NB) ? g_part[t] : 0;
    int lane = t & 31, w = t >> 5;
    int inc = v;
    #pragma unroll
    for (int o = 1; o < 32; o <<= 1) {
        int u = __shfl_up_sync(0xffffffffu, inc, o);
        if (lane >= o) inc += u;
    }
    if (lane == 31) wpre[w] = inc;
    __syncthreads();
    if (w == 0) {
        int s = (lane < 8) ? wpre[lane] : 0;
        int si = s;
        #pragma unroll
        for (int o = 1; o < 8; o <<= 1) {
            int u = __shfl_up_sync(0xffffffffu, si, o);
            if (lane >= o) si += u;
        }
        if (lane < 8) wpre[lane] = si - s;
        if (lane == 7) g_off[NN] = si;
    }
    __syncthreads();
    if (t < SCAN_NB) g_ppre[t] = wpre[w] + inc - v;
}

__global__ void scan_offsets_kernel() {
    __shared__ int wpre[SCAN_B / 32];
    int i = blockIdx.x * SCAN_B + threadIdx.x;
    int v = (i < NN) ? g_cur[i] : 0;
    int lane = threadIdx.x & 31, w = threadIdx.x >> 5;
    int inc = v;
    #pragma unroll
    for (int o = 1; o < 32; o <<= 1) {
        int u = __shfl_up_sync(0xffffffffu, inc, o);
        if (lane >= o) inc += u;
    }
    if (lane == 31) wpre[w] = inc;
    __syncthreads();
    if (w == 0) {
        int s = (lane < SCAN_B / 32) ? wpre[lane] : 0;
        int si = s;
        #pragma unroll
        for (int o = 1; o < 8; o <<= 1) {
            int u = __shfl_up_sync(0xffffffffu, si, o);
            if (lane >= o) si += u;
        }
        if (lane < SCAN_B / 32) wpre[lane] = si - s;
    }
    __syncthreads();
    if (i < NN) {
        int o = g_ppre[blockIdx.x] + wpre[w] + (inc - v);
        g_off[i] = o;
        g_cur[i] = o;
    }
}

__global__ void bucket_kernel(const int* __restrict__ ei) {
    int e = blockIdx.x * blockDim.x + threadIdx.x;
    if (e < EE) {
        int d = ei[EE + e];
        int p = atomicAdd(&g_cur[d], 1);
        g_srcs[p] = ei[e];
    }
}

// ---------------- GEMM1 via mma.sync bf16 hi/lo split -----------------------
// CTA: 64 rows x 128 cols, K=128. 8 warps = 4(M) x 2(N); warp = 16x64.
// smem: A_hi/A_lo 64x136 bf16, B_hi/B_lo (=W1^T) 128x136 bf16; pitch 272B
// makes ldmatrix row-groups bank-conflict-free.
#define MMA_PITCH 272
__global__ void __launch_bounds__(256)
mma_gemm1_kernel(const float* __restrict__ x, const float* __restrict__ W1) {
    extern __shared__ char smem[];
    const int A_HI = 0, A_LO = 17408, B_HI = 34816, B_LO = 69632;
    uint32_t sb = smem_u32(smem);
    int t = threadIdx.x, lane = t & 31, w = t >> 5;
    int rowBase = blockIdx.x * 64;

    // B = W1^T hi/lo  (W1 read coalesced; smem writes scattered, one-time)
    for (int i = t; i < 16384; i += 256) {
        int k = i >> 7, n = i & 127;
        float v = W1[i];
        __nv_bfloat16 h = __float2bfloat16(v);
        __nv_bfloat16 l = __float2bfloat16(v - __bfloat162float(h));
        *(__nv_bfloat16*)(smem + B_HI + n * MMA_PITCH + k * 2) = h;
        *(__nv_bfloat16*)(smem + B_LO + n * MMA_PITCH + k * 2) = l;
    }
    // A rows hi/lo
    for (int i = t; i < 8192; i += 256) {
        int m = i >> 7, k = i & 127;
        int gr = rowBase + m;
        float v = (gr < NN) ? x[(size_t)gr * 128 + k] : 0.0f;
        __nv_bfloat16 h = __float2bfloat16(v);
        __nv_bfloat16 l = __float2bfloat16(v - __bfloat162float(h));
        *(__nv_bfloat16*)(smem + A_HI + m * MMA_PITCH + k * 2) = h;
        *(__nv_bfloat16*)(smem + A_LO + m * MMA_PITCH + k * 2) = l;
    }
    __syncthreads();

    int wm = w & 3, wn = w >> 2;
    float acc[8][4];
    #pragma unroll
    for (int j = 0; j < 8; j++)
        #pragma unroll
        for (int c = 0; c < 4; c++) acc[j][c] = 0.0f;

    // ldmatrix lane address bases
    uint32_t aRow = (uint32_t)(wm * 16 + (lane & 7) + ((lane >> 3) & 1) * 8);
    uint32_t aOff = aRow * MMA_PITCH + (uint32_t)(lane >> 4) * 16u;
    uint32_t aHiA = sb + A_HI + aOff;
    uint32_t aLoA = sb + A_LO + aOff;
    uint32_t bg = lane >> 3, br = lane & 7;
    uint32_t bRowOff = ((bg >> 1) * 8u + br) * MMA_PITCH + (bg & 1u) * 16u;

    #pragma unroll
    for (int ks = 0; ks < 8; ks++) {
        uint32_t k2 = (uint32_t)ks * 32u;          // k0*2 bytes
        uint32_t ah[4], al[4];
        LDSM_X4(ah[0], ah[1], ah[2], ah[3], aHiA + k2);
        LDSM_X4(al[0], al[1], al[2], al[3], aLoA + k2);
        #pragma unroll
        for (int jj = 0; jj < 4; jj++) {
            uint32_t nOff = (uint32_t)(wn * 64 + jj * 16) * MMA_PITCH;
            uint32_t bh[4], bl[4];
            LDSM_X4(bh[0], bh[1], bh[2], bh[3], sb + B_HI + nOff + bRowOff + k2);
            LDSM_X4(bl[0], bl[1], bl[2], bl[3], sb + B_LO + nOff + bRowOff + k2);
            MMA_BF16(acc[2 * jj],     ah, bh[0], bh[1]);   // hi*hi
            MMA_BF16(acc[2 * jj],     ah, bl[0], bl[1]);   // hi*lo
            MMA_BF16(acc[2 * jj],     al, bh[0], bh[1]);   // lo*hi
            MMA_BF16(acc[2 * jj + 1], ah, bh[2], bh[3]);
            MMA_BF16(acc[2 * jj + 1], ah, bl[2], bl[3]);
            MMA_BF16(acc[2 * jj + 1], al, bh[2], bh[3]);
        }
    }

    // epilogue: c-frag rows l/4 and l/4+8, cols 2*(l%4)
    int r0 = rowBase + wm * 16 + (lane >> 2);
    int col = wn * 64 + (lane & 3) * 2;
    #pragma unroll
    for (int j = 0; j < 8; j++) {
        if (r0 < NN)
            *(float2*)&g_y[(size_t)r0 * 128 + col + j * 8] =
                make_float2(acc[j][0], acc[j][1]);
        if (r0 + 8 < NN)
            *(float2*)&g_y[(size_t)(r0 + 8) * 128 + col + j * 8] =
                make_float2(acc[j][2], acc[j][3]);
    }
}

// ---------------- GEMM2 (FFMA): g_z = g_h @ W2[128,64] ----------------------
__global__ void __launch_bounds__(256)
gemm2_kernel(const float* __restrict__ W, int M) {
    __shared__ __align__(16) float As[64][20];
    __shared__ __align__(16) float Ws[16 * 64];

    const float* __restrict__ A = g_h;
    float* __restrict__ C = g_z;

    int t  = threadIdx.x;
    int rg = t >> 5;
    int cl = t & 31;
    int rowBase = blockIdx.x * 64;

    float acc[8][2];
    #pragma unroll
    for (int r = 0; r < 8; r++) { acc[r][0] = 0.f; acc[r][1] = 0.f; }

    for (int k0 = 0; k0 < 128; k0 += 16) {
        {
            int r = t >> 2, q = t & 3;
            int grow = rowBase + r;
            float4 v = make_float4(0.f, 0.f, 0.f, 0.f);
            if (grow < M) v = *(const float4*)&A[(size_t)grow * 128 + k0 + q * 4];
            *(float4*)&As[r][q * 4] = v;
        }
        {
            const float4* Wg = (const float4*)W;
            ((float4*)Ws)[t] = Wg[(k0 * 64) / 4 + t];
        }
        __syncthreads();
        #pragma unroll
        for (int kq = 0; kq < 4; kq++) {
            float2 a_ = *(const float2*)&Ws[(kq * 4 + 0) * 64 + cl * 2];
            float2 b_ = *(const float2*)&Ws[(kq * 4 + 1) * 64 + cl * 2];
            float2 c_ = *(const float2*)&Ws[(kq * 4 + 2) * 64 + cl * 2];
            float2 d_ = *(const float2*)&Ws[(kq * 4 + 3) * 64 + cl * 2];
            float w0[2] = {a_.x, a_.y};
            float w1[2] = {b_.x, b_.y};
            float w2[2] = {c_.x, c_.y};
            float w3[2] = {d_.x, d_.y};
            #pragma unroll
            for (int r = 0; r < 8; r++) {
                float4 a = *(const float4*)&As[rg * 8 + r][kq * 4];
                #pragma unroll
                for (int c = 0; c < 2; c++) {
                    acc[r][c] = fmaf(a.x, w0[c], acc[r][c]);
                    acc[r][c] = fmaf(a.y, w1[c], acc[r][c]);
                    acc[r][c] = fmaf(a.z, w2[c], acc[r][c]);
                    acc[r][c] = fmaf(a.w, w3[c], acc[r][c]);
                }
            }
        }
        __syncthreads();
    }
    #pragma unroll
    for (int r = 0; r < 8; r++) {
        int grow = rowBase + rg * 8 + r;
        if (grow < M) {
            float2 v = make_float2(acc[r][0], acc[r][1]);
            *(float2*)&C[(size_t)grow * 64 + cl * 2] = v;
        }
    }
}

// ---------------- layer-1 aggregate + bias + ReLU + dropout ----------------
__global__ void __launch_bounds__(256)
agg_relu_drop_kernel(const float* __restrict__ b1) {
    int gw = (blockIdx.x * blockDim.x + threadIdx.x) >> 5;
    if (gw >= NN) return;
    int lane = threadIdx.x & 31;

    const float4* Y = (const float4*)g_y;
    float4 acc = Y[(size_t)gw * 32 + lane];
    float4 bb  = ((const float4*)b1)[lane];
    const float c1 = 1.0f + EPSV;
    acc.x = fmaf(acc.x, c1, bb.x);
    acc.y = fmaf(acc.y, c1, bb.y);
    acc.z = fmaf(acc.z, c1, bb.z);
    acc.w = fmaf(acc.w, c1, bb.w);

    int j = g_off[gw], end = g_off[gw + 1];
    for (; j + 4 <= end; j += 4) {
        int s0 = g_srcs[j], s1 = g_srcs[j + 1], s2 = g_srcs[j + 2], s3 = g_srcs[j + 3];
        float4 v0 = Y[(size_t)s0 * 32 + lane];
        float4 v1 = Y[(size_t)s1 * 32 + lane];
        float4 v2 = Y[(size_t)s2 * 32 + lane];
        float4 v3 = Y[(size_t)s3 * 32 + lane];
        acc.x += (v0.x + v1.x) + (v2.x + v3.x);
        acc.y += (v0.y + v1.y) + (v2.y + v3.y);
        acc.z += (v0.z + v1.z) + (v2.z + v3.z);
        acc.w += (v0.w + v1.w) + (v2.w + v3.w);
    }
    for (; j < end; j++) {
        float4 v = Y[(size_t)g_srcs[j] * 32 + lane];
        acc.x += v.x; acc.y += v.y; acc.z += v.z; acc.w += v.w;
    }

    acc.x = fmaxf(acc.x, 0.f);
    acc.y = fmaxf(acc.y, 0.f);
    acc.z = fmaxf(acc.z, 0.f);
    acc.w = fmaxf(acc.w, 0.f);

    uint32_t base = (uint32_t)gw * 128u + (uint32_t)lane * 4u;
    acc.x *= drop_scale(base + 0u);
    acc.y *= drop_scale(base + 1u);
    acc.z *= drop_scale(base + 2u);
    acc.w *= drop_scale(base + 3u);

    ((float4*)g_h)[(size_t)gw * 32 + lane] = acc;
}

// ---------------- layer-2 aggregate + bias -> output -----------------------
__global__ void __launch_bounds__(256)
agg_out_kernel(const float* __restrict__ b2, float* __restrict__ out) {
    int gw = (blockIdx.x * blockDim.x + threadIdx.x) >> 5;
    if (gw >= NN) return;
    int lane = threadIdx.x & 31;

    const float2* Z = (const float2*)g_z;
    float2 acc = Z[(size_t)gw * 32 + lane];
    float2 bb  = ((const float2*)b2)[lane];
    const float c1 = 1.0f + EPSV;
    acc.x = fmaf(acc.x, c1, bb.x);
    acc.y = fmaf(acc.y, c1, bb.y);

    int j = g_off[gw], end = g_off[gw + 1];
    for (; j + 4 <= end; j += 4) {
        int s0 = g_srcs[j], s1 = g_srcs[j + 1], s2 = g_srcs[j + 2], s3 = g_srcs[j + 3];
        float2 v0 = Z[(size_t)s0 * 32 + lane];
        float2 v1 = Z[(size_t)s1 * 32 + lane];
        float2 v2 = Z[(size_t)s2 * 32 + lane];
        float2 v3 = Z[(size_t)s3 * 32 + lane];
        acc.x += (v0.x + v1.x) + (v2.x + v3.x);
        acc.y += (v0.y + v1.y) + (v2.y + v3.y);
    }
    for (; j < end; j++) {
        float2 v = Z[(size_t)g_srcs[j] * 32 + lane];
        acc.x += v.x; acc.y += v.y;
    }

    ((float2*)out)[(size_t)gw * 32 + lane] = acc;
}

// ---------------- launch -----------------------------------------------------
extern "C" void kernel_launch(void* const* d_in, const int* in_sizes, int n_in,
                              void* d_out, int out_size) {
    const float* x  = (const float*)d_in[0];
    const int*   ei = (const int*)d_in[1];     // int32 (JAX x64 disabled)
    const float* W1 = (const float*)d_in[2];
    const float* b1 = (const float*)d_in[3];
    const float* W2 = (const float*)d_in[4];
    const float* b2 = (const float*)d_in[5];
    float*       out = (float*)d_out;

    const int MMA_SMEM = 104448;   // A hi/lo (2x17408) + B hi/lo (2x34816)
    cudaFuncSetAttribute(mma_gemm1_kernel,
                         cudaFuncAttributeMaxDynamicSharedMemorySize, MMA_SMEM);

    // ONE side stream + events (capture-safe fork/join; not destroyed —
    // destroying during active capture invalidates it; stays in driver pool).
    cudaStream_t s2;
    cudaStreamCreate(&s2);
    cudaEvent_t eFork, eCSR;
    cudaEventCreateWithFlags(&eFork, cudaEventDisableTiming);
    cudaEventCreateWithFlags(&eCSR,  cudaEventDisableTiming);

    cudaEventRecord(eFork, 0);
    cudaStreamWaitEvent(s2, eFork, 0);

    // branch A (s2): CSR build
    zero_deg_kernel<<<(NN + 255) / 256, 256, 0, s2>>>();
    hist_kernel<<<(EE + 255) / 256, 256, 0, s2>>>(ei);
    scan_partial_kernel<<<SCAN_NB, SCAN_B, 0, s2>>>();
    scan_tops_kernel<<<1, 256, 0, s2>>>();
    scan_offsets_kernel<<<SCAN_NB, SCAN_B, 0, s2>>>();
    bucket_kernel<<<(EE + 255) / 256, 256, 0, s2>>>(ei);
    cudaEventRecord(eCSR, s2);

    // branch B (default): y = x@W1 on tensor cores (mma.sync bf16 hi/lo)
    mma_gemm1_kernel<<<(NN + 63) / 64, 256, MMA_SMEM>>>(x, W1);

    // join
    cudaStreamWaitEvent(0, eCSR, 0);

    // layer 1 finish: h = dropout(relu((1+eps)y + seg_sum(y[src]) + b1))
    agg_relu_drop_kernel<<<(NN * 32 + 255) / 256, 256>>>(b1);

    // layer 2: z = h@W2 ; out = (1+eps)z + seg_sum(z[src]) + b2
    gemm2_kernel<<<(NN + 63) / 64, 256>>>(W2, NN);
    agg_out_kernel<<<(NN * 32 + 255) / 256, 256>>>(b2, out);
}

// round 14
// speedup vs baseline: 1.6583x; 1.0607x over previous
#include <cuda_runtime.h>
#include <cuda_bf16.h>
#include <cstdint>

#define NN   50000
#define EE   600000
#define FIN  128
#define HID  128
#define OUTC 64
#define EPSV 1e-9f

#define SCAN_B 256
#define SCAN_NB ((NN + SCAN_B - 1) / SCAN_B)   // 196

// ---------------- scratch (static device globals; no runtime allocation) ----
__device__ int   g_off [NN + 1];
__device__ int   g_cur [NN];
__device__ int   g_part[SCAN_NB];
__device__ int   g_ppre[SCAN_NB];
__device__ int   g_srcs[EE];
__device__ __align__(16) float g_y[(size_t)NN * HID];
__device__ __align__(16) float g_h[(size_t)NN * HID];
__device__ __align__(16) float g_z[(size_t)NN * OUTC];

// ---------------- threefry2x32, key = (0, 42) -------------------------------
__device__ __forceinline__ uint32_t tf_rotl(uint32_t x, int d) {
    return __funnelshift_l(x, x, d);
}

__device__ __forceinline__ uint32_t tf_bits32(uint32_t i) {
    const uint32_t k0 = 0u, k1 = 42u;
    const uint32_t k2 = 0u ^ 42u ^ 0x1BD11BDAu;
    uint32_t v0 = 0u + k0;
    uint32_t v1 = i  + k1;
#define TF_R(r) { v0 += v1; v1 = tf_rotl(v1, r); v1 ^= v0; }
    TF_R(13) TF_R(15) TF_R(26) TF_R(6)  v0 += k1; v1 += k2 + 1u;
    TF_R(17) TF_R(29) TF_R(16) TF_R(24) v0 += k2; v1 += k0 + 2u;
    TF_R(13) TF_R(15) TF_R(26) TF_R(6)  v0 += k0; v1 += k1 + 3u;
    TF_R(17) TF_R(29) TF_R(16) TF_R(24) v0 += k1; v1 += k2 + 4u;
    TF_R(13) TF_R(15) TF_R(26) TF_R(6)  v0 += k2; v1 += k0 + 5u;
#undef TF_R
    return v0 ^ v1;
}

__device__ __forceinline__ float drop_scale(uint32_t idx) {
    return (tf_bits32(idx) >> 31) ? 0.0f : 2.0f;
}

// ---------------- warp-MMA helpers (sm_80-era path; valid on compute_103) ---
__device__ __forceinline__ uint32_t smem_u32(const void* p) {
    uint32_t a;
    asm("{ .reg .u64 t; cvta.to.shared.u64 t, %1; cvt.u32.u64 %0, t; }"
        : "=r"(a) : "l"(p));
    return a;
}

#define LDSM_X4(r0, r1, r2, r3, addr) \
    asm volatile("ldmatrix.sync.aligned.m8n8.x4.shared.b16 {%0,%1,%2,%3}, [%4];" \
        : "=r"(r0), "=r"(r1), "=r"(r2), "=r"(r3) : "r"(addr))

#define MMA_BF16(d, a, b0, b1) \
    asm volatile("mma.sync.aligned.m16n8k16.row.col.f32.bf16.bf16.f32 " \
        "{%0,%1,%2,%3}, {%4,%5,%6,%7}, {%8,%9}, {%0,%1,%2,%3};" \
        : "+f"((d)[0]), "+f"((d)[1]), "+f"((d)[2]), "+f"((d)[3]) \
        : "r"((a)[0]), "r"((a)[1]), "r"((a)[2]), "r"((a)[3]), \
          "r"(b0), "r"(b1))

// ---------------- CSR build (edge_index is int32: src=[0,E), dst=[E,2E)) ---
__global__ void zero_deg_kernel() {
    int i = blockIdx.x * blockDim.x + threadIdx.x;
    if (i < NN) g_cur[i] = 0;
}

__global__ void hist_kernel(const int* __restrict__ ei) {
    int e = blockIdx.x * blockDim.x + threadIdx.x;
    if (e < EE) atomicAdd(&g_cur[ei[EE + e]], 1);
}

__global__ void scan_partial_kernel() {
    __shared__ int wsum[SCAN_B / 32];
    int i = blockIdx.x * SCAN_B + threadIdx.x;
    int v = (i < NN) ? g_cur[i] : 0;
    int s = v;
    #pragma unroll
    for (int o = 16; o > 0; o >>= 1) s += __shfl_down_sync(0xffffffffu, s, o);
    int lane = threadIdx.x & 31, w = threadIdx.x >> 5;
    if (lane == 0) wsum[w] = s;
    __syncthreads();
    if (w == 0) {
        int t = (lane < SCAN_B / 32) ? wsum[lane] : 0;
        #pragma unroll
        for (int o = 4; o > 0; o >>= 1) t += __shfl_down_sync(0xffffffffu, t, o);
        if (lane == 0) g_part[blockIdx.x] = t;
    }
}

__global__ void scan_tops_kernel() {
    __shared__ int wpre[8];
    int t = threadIdx.x;
    int v = (t < SCAN_NB) ? g_part[t] : 0;
    int lane = t & 31, w = t >> 5;
    int inc = v;
    #pragma unroll
    for (int o = 1; o < 32; o <<= 1) {
        int u = __shfl_up_sync(0xffffffffu, inc, o);
        if (lane >= o) inc += u;
    }
    if (lane == 31) wpre[w] = inc;
    __syncthreads();
    if (w == 0) {
        int s = (lane < 8) ? wpre[lane] : 0;
        int si = s;
        #pragma unroll
        for (int o = 1; o < 8; o <<= 1) {
            int u = __shfl_up_sync(0xffffffffu, si, o);
            if (lane >= o) si += u;
        }
        if (lane < 8) wpre[lane] = si - s;
        if (lane == 7) g_off[NN] = si;
    }
    __syncthreads();
    if (t < SCAN_NB) g_ppre[t] = wpre[w] + inc - v;
}

__global__ void scan_offsets_kernel() {
    __shared__ int wpre[SCAN_B / 32];
    int i = blockIdx.x * SCAN_B + threadIdx.x;
    int v = (i < NN) ? g_cur[i] : 0;
    int lane = threadIdx.x & 31, w = threadIdx.x >> 5;
    int inc = v;
    #pragma unroll
    for (int o = 1; o < 32; o <<= 1) {
        int u = __shfl_up_sync(0xffffffffu, inc, o);
        if (lane >= o) inc += u;
    }
    if (lane == 31) wpre[w] = inc;
    __syncthreads();
    if (w == 0) {
        int s = (lane < SCAN_B / 32) ? wpre[lane] : 0;
        int si = s;
        #pragma unroll
        for (int o = 1; o < 8; o <<= 1) {
            int u = __shfl_up_sync(0xffffffffu, si, o);
            if (lane >= o) si += u;
        }
        if (lane < SCAN_B / 32) wpre[lane] = si - s;
    }
    __syncthreads();
    if (i < NN) {
        int o = g_ppre[blockIdx.x] + wpre[w] + (inc - v);
        g_off[i] = o;
        g_cur[i] = o;
    }
}

__global__ void bucket_kernel(const int* __restrict__ ei) {
    int e = blockIdx.x * blockDim.x + threadIdx.x;
    if (e < EE) {
        int d = ei[EE + e];
        int p = atomicAdd(&g_cur[d], 1);
        g_srcs[p] = ei[e];
    }
}

// ---------------- GEMM via mma.sync bf16 hi/lo split ------------------------
// CTA: 64 rows x NC cols, K=128. 8 warps = 4(M) x 2(N); warp = 16 x NC/2.
// smem pitch 272B -> ldmatrix row-groups bank-conflict-free.
// LAYER2: A = g_h, C = g_z; else A = x arg, C = g_y. W is K-major [128, NC].
#define MMA_PITCH 272
template <int NC, bool LAYER2>
__global__ void __launch_bounds__(256)
mma_gemm_kernel(const float* __restrict__ A_arg, const float* __restrict__ W) {
    extern __shared__ char smem[];
    constexpr int JJ = NC / 32;               // 16-col blocks per warp
    constexpr int A_TILE = 64 * MMA_PITCH;    // 17408
    constexpr int B_TILE = NC * MMA_PITCH;
    const int A_HI = 0, A_LO = A_TILE, B_HI = 2 * A_TILE, B_LO = 2 * A_TILE + B_TILE;
    uint32_t sb = smem_u32(smem);
    int t = threadIdx.x, lane = t & 31, w = t >> 5;
    int rowBase = blockIdx.x * 64;

    const float* __restrict__ A = LAYER2 ? (const float*)g_h : A_arg;
    float* __restrict__ C       = LAYER2 ? g_z : g_y;

    // B = W^T hi/lo  (W read coalesced; smem writes scattered, one-time)
    for (int i = t; i < 128 * NC; i += 256) {
        int k = i / NC, n = i % NC;
        float v = W[i];
        __nv_bfloat16 h = __float2bfloat16(v);
        __nv_bfloat16 l = __float2bfloat16(v - __bfloat162float(h));
        *(__nv_bfloat16*)(smem + B_HI + n * MMA_PITCH + k * 2) = h;
        *(__nv_bfloat16*)(smem + B_LO + n * MMA_PITCH + k * 2) = l;
    }
    // A rows hi/lo
    for (int i = t; i < 8192; i += 256) {
        int m = i >> 7, k = i & 127;
        int gr = rowBase + m;
        float v = (gr < NN) ? A[(size_t)gr * 128 + k] : 0.0f;
        __nv_bfloat16 h = __float2bfloat16(v);
        __nv_bfloat16 l = __float2bfloat16(v - __bfloat162float(h));
        *(__nv_bfloat16*)(smem + A_HI + m * MMA_PITCH + k * 2) = h;
        *(__nv_bfloat16*)(smem + A_LO + m * MMA_PITCH + k * 2) = l;
    }
    __syncthreads();

    int wm = w & 3, wn = w >> 2;
    float acc[2 * JJ][4];
    #pragma unroll
    for (int j = 0; j < 2 * JJ; j++)
        #pragma unroll
        for (int c = 0; c < 4; c++) acc[j][c] = 0.0f;

    // ldmatrix lane address bases
    uint32_t aRow = (uint32_t)(wm * 16 + (lane & 7) + ((lane >> 3) & 1) * 8);
    uint32_t aOff = aRow * MMA_PITCH + (uint32_t)(lane >> 4) * 16u;
    uint32_t aHiA = sb + A_HI + aOff;
    uint32_t aLoA = sb + A_LO + aOff;
    uint32_t bg = lane >> 3, br = lane & 7;
    uint32_t bRowOff = ((bg >> 1) * 8u + br) * MMA_PITCH + (bg & 1u) * 16u;

    #pragma unroll
    for (int ks = 0; ks < 8; ks++) {
        uint32_t k2 = (uint32_t)ks * 32u;          // k0*2 bytes
        uint32_t ah[4], al[4];
        LDSM_X4(ah[0], ah[1], ah[2], ah[3], aHiA + k2);
        LDSM_X4(al[0], al[1], al[2], al[3], aLoA + k2);
        #pragma unroll
        for (int jj = 0; jj < JJ; jj++) {
            uint32_t nOff = (uint32_t)(wn * (NC / 2) + jj * 16) * MMA_PITCH;
            uint32_t bh[4], bl[4];
            LDSM_X4(bh[0], bh[1], bh[2], bh[3], sb + B_HI + nOff + bRowOff + k2);
            LDSM_X4(bl[0], bl[1], bl[2], bl[3], sb + B_LO + nOff + bRowOff + k2);
            MMA_BF16(acc[2 * jj],     ah, bh[0], bh[1]);   // hi*hi
            MMA_BF16(acc[2 * jj],     ah, bl[0], bl[1]);   // hi*lo
            MMA_BF16(acc[2 * jj],     al, bh[0], bh[1]);   // lo*hi
            MMA_BF16(acc[2 * jj + 1], ah, bh[2], bh[3]);
            MMA_BF16(acc[2 * jj + 1], ah, bl[2], bl[3]);
            MMA_BF16(acc[2 * jj + 1], al, bh[2], bh[3]);
        }
    }

    // epilogue: c-frag rows l/4 and l/4+8, cols 2*(l%4)
    int r0 = rowBase + wm * 16 + (lane >> 2);
    int col = wn * (NC / 2) + (lane & 3) * 2;
    #pragma unroll
    for (int j = 0; j < 2 * JJ; j++) {
        if (r0 < NN)
            *(float2*)&C[(size_t)r0 * NC + col + j * 8] =
                make_float2(acc[j][0], acc[j][1]);
        if (r0 + 8 < NN)
            *(float2*)&C[(size_t)(r0 + 8) * NC + col + j * 8] =
                make_float2(acc[j][2], acc[j][3]);
    }
}

// ---------------- layer-1 aggregate + bias + ReLU + dropout ----------------
__global__ void __launch_bounds__(256)
agg_relu_drop_kernel(const float* __restrict__ b1) {
    int gw = (blockIdx.x * blockDim.x + threadIdx.x) >> 5;
    if (gw >= NN) return;
    int lane = threadIdx.x & 31;

    const float4* Y = (const float4*)g_y;
    float4 acc = Y[(size_t)gw * 32 + lane];
    float4 bb  = ((const float4*)b1)[lane];
    const float c1 = 1.0f + EPSV;
    acc.x = fmaf(acc.x, c1, bb.x);
    acc.y = fmaf(acc.y, c1, bb.y);
    acc.z = fmaf(acc.z, c1, bb.z);
    acc.w = fmaf(acc.w, c1, bb.w);

    int j = g_off[gw], end = g_off[gw + 1];
    for (; j + 4 <= end; j += 4) {
        int s0 = g_srcs[j], s1 = g_srcs[j + 1], s2 = g_srcs[j + 2], s3 = g_srcs[j + 3];
        float4 v0 = Y[(size_t)s0 * 32 + lane];
        float4 v1 = Y[(size_t)s1 * 32 + lane];
        float4 v2 = Y[(size_t)s2 * 32 + lane];
        float4 v3 = Y[(size_t)s3 * 32 + lane];
        acc.x += (v0.x + v1.x) + (v2.x + v3.x);
        acc.y += (v0.y + v1.y) + (v2.y + v3.y);
        acc.z += (v0.z + v1.z) + (v2.z + v3.z);
        acc.w += (v0.w + v1.w) + (v2.w + v3.w);
    }
    for (; j < end; j++) {
        float4 v = Y[(size_t)g_srcs[j] * 32 + lane];
        acc.x += v.x; acc.y += v.y; acc.z += v.z; acc.w += v.w;
    }

    acc.x = fmaxf(acc.x, 0.f);
    acc.y = fmaxf(acc.y, 0.f);
    acc.z = fmaxf(acc.z, 0.f);
    acc.w = fmaxf(acc.w, 0.f);

    uint32_t base = (uint32_t)gw * 128u + (uint32_t)lane * 4u;
    acc.x *= drop_scale(base + 0u);
    acc.y *= drop_scale(base + 1u);
    acc.z *= drop_scale(base + 2u);
    acc.w *= drop_scale(base + 3u);

    ((float4*)g_h)[(size_t)gw * 32 + lane] = acc;
}

// ---------------- layer-2 aggregate + bias -> output -----------------------
__global__ void __launch_bounds__(256)
agg_out_kernel(const float* __restrict__ b2, float* __restrict__ out) {
    int gw = (blockIdx.x * blockDim.x + threadIdx.x) >> 5;
    if (gw >= NN) return;
    int lane = threadIdx.x & 31;

    const float2* Z = (const float2*)g_z;
    float2 acc = Z[(size_t)gw * 32 + lane];
    float2 bb  = ((const float2*)b2)[lane];
    const float c1 = 1.0f + EPSV;
    acc.x = fmaf(acc.x, c1, bb.x);
    acc.y = fmaf(acc.y, c1, bb.y);

    int j = g_off[gw], end = g_off[gw + 1];
    for (; j + 4 <= end; j += 4) {
        int s0 = g_srcs[j], s1 = g_srcs[j + 1], s2 = g_srcs[j + 2], s3 = g_srcs[j + 3];
        float2 v0 = Z[(size_t)s0 * 32 + lane];
        float2 v1 = Z[(size_t)s1 * 32 + lane];
        float2 v2 = Z[(size_t)s2 * 32 + lane];
        float2 v3 = Z[(size_t)s3 * 32 + lane];
        acc.x += (v0.x + v1.x) + (v2.x + v3.x);
        acc.y += (v0.y + v1.y) + (v2.y + v3.y);
    }
    for (; j < end; j++) {
        float2 v = Z[(size_t)g_srcs[j] * 32 + lane];
        acc.x += v.x; acc.y += v.y;
    }

    ((float2*)out)[(size_t)gw * 32 + lane] = acc;
}

// ---------------- launch -----------------------------------------------------
extern "C" void kernel_launch(void* const* d_in, const int* in_sizes, int n_in,
                              void* d_out, int out_size) {
    const float* x  = (const float*)d_in[0];
    const int*   ei = (const int*)d_in[1];     // int32 (JAX x64 disabled)
    const float* W1 = (const float*)d_in[2];
    const float* b1 = (const float*)d_in[3];
    const float* W2 = (const float*)d_in[4];
    const float* b2 = (const float*)d_in[5];
    float*       out = (float*)d_out;

    const int SMEM1 = 104448;   // A hi/lo (2x17408) + B hi/lo (2x34816)
    const int SMEM2 = 69632;    // A hi/lo (2x17408) + B hi/lo (2x17408)
    cudaFuncSetAttribute((const void*)mma_gemm_kernel<128, false>,
                         cudaFuncAttributeMaxDynamicSharedMemorySize, SMEM1);
    cudaFuncSetAttribute((const void*)mma_gemm_kernel<64, true>,
                         cudaFuncAttributeMaxDynamicSharedMemorySize, SMEM2);

    // ONE side stream + events (capture-safe fork/join; not destroyed —
    // destroying during active capture invalidates it; stays in driver pool).
    cudaStream_t s2;
    cudaStreamCreate(&s2);
    cudaEvent_t eFork, eCSR;
    cudaEventCreateWithFlags(&eFork, cudaEventDisableTiming);
    cudaEventCreateWithFlags(&eCSR,  cudaEventDisableTiming);

    cudaEventRecord(eFork, 0);
    cudaStreamWaitEvent(s2, eFork, 0);

    // branch A (s2): CSR build
    zero_deg_kernel<<<(NN + 255) / 256, 256, 0, s2>>>();
    hist_kernel<<<(EE + 255) / 256, 256, 0, s2>>>(ei);
    scan_partial_kernel<<<SCAN_NB, SCAN_B, 0, s2>>>();
    scan_tops_kernel<<<1, 256, 0, s2>>>();
    scan_offsets_kernel<<<SCAN_NB, SCAN_B, 0, s2>>>();
    bucket_kernel<<<(EE + 255) / 256, 256, 0, s2>>>(ei);
    cudaEventRecord(eCSR, s2);

    // branch B (default): y = x@W1 on tensor cores (mma.sync bf16 hi/lo)
    mma_gemm_kernel<128, false><<<(NN + 63) / 64, 256, SMEM1>>>(x, W1);

    // join
    cudaStreamWaitEvent(0, eCSR, 0);

    // layer 1 finish: h = dropout(relu((1+eps)y + seg_sum(y[src]) + b1))
    agg_relu_drop_kernel<<<(NN * 32 + 255) / 256, 256>>>(b1);

    // layer 2: z = h@W2 (tensor cores) ; out = (1+eps)z + seg_sum(z[src]) + b2
    mma_gemm_kernel<64, true><<<(NN + 63) / 64, 256, SMEM2>>>(nullptr, W2);
    agg_out_kernel<<<(NN * 32 + 255) / 256, 256>>>(b2, out);
}